// round 15
// baseline (speedup 1.0000x reference)
#include <cuda_runtime.h>
#include <cuda_bf16.h>
#include <cuda_fp16.h>

#define TT 2000
#define NB 64
#define VV 1000
#define ROWS (TT * NB)
#define NEG_BIG (-1e30f)
#define TPB 1024
#define KITER 2           // ceil(TT / TPB)
#define NWARP (TPB / 32)  // 32
#define FULLM 0xffffffffu

// Scratch (no allocation allowed). n-major packed:
//   lo16 = argmax (V=1000 < 65536), hi16 = fp16 bits of maxlp.
__device__ unsigned g_packed[NB * TT];

// ---------------------------------------------------------------------------
// Kernel A: warp-per-row reduction over V=1000. Pure streaming: only ONE
// 4-byte scratch store per warp; default paths moved to kernel B.
// ---------------------------------------------------------------------------
__global__ __launch_bounds__(256) void rowreduce_kernel(
    const float* __restrict__ logits)
{
    const int row  = blockIdx.x * 8 + (threadIdx.x >> 5);  // row = t*NB + n
    const int lane = threadIdx.x & 31;

    const float4* __restrict__ p =
        reinterpret_cast<const float4*>(logits + (size_t)row * VV);

    // V=1000 floats = 250 float4; lane takes indices lane + 32*j, j<8.
    float4 v[8];
#pragma unroll
    for (int j = 0; j < 8; j++) {
        int idx = lane + 32 * j;
        if (idx < 250) v[j] = p[idx];
        else           v[j] = make_float4(NEG_BIG, NEG_BIG, NEG_BIG, NEG_BIG);
    }

    float m = NEG_BIG; int am = 0;
#pragma unroll
    for (int j = 0; j < 8; j++) {
        int base = (lane + 32 * j) * 4;
        float x;
        x = v[j].x; if (x > m) { m = x; am = base;     }
        x = v[j].y; if (x > m) { m = x; am = base + 1; }
        x = v[j].z; if (x > m) { m = x; am = base + 2; }
        x = v[j].w; if (x > m) { m = x; am = base + 3; }
    }
#pragma unroll
    for (int off = 16; off; off >>= 1) {
        float om = __shfl_xor_sync(FULLM, m,  off);
        int   oa = __shfl_xor_sync(FULLM, am, off);
        if (om > m || (om == m && oa < am)) { m = om; am = oa; }
    }

    float s = 0.f;
#pragma unroll
    for (int j = 0; j < 8; j++) {
        s += __expf(v[j].x - m) + __expf(v[j].y - m)
           + __expf(v[j].z - m) + __expf(v[j].w - m);
    }
#pragma unroll
    for (int off = 16; off; off >>= 1)
        s += __shfl_xor_sync(FULLM, s, off);

    if (lane == 0) {
        float maxlp = -__logf(s);            // max - lse
        int t = row >> 6;                    // NB == 64
        int n = row & (NB - 1);
        unsigned hb = (unsigned)__half_as_ushort(__float2half_rn(maxlp));
        g_packed[n * TT + t] = (hb << 16) | (unsigned)am;
    }
}

// ---------------------------------------------------------------------------
// Kernel B (PDL secondary): block-per-n. Writes full default paths, then
// compacted prefix, score, out_lens.
// ---------------------------------------------------------------------------
__global__ __launch_bounds__(TPB) void compact_kernel(
    const int* __restrict__ in_lens, float* __restrict__ out)
{
    __shared__ int   sh_a[TPB];
    __shared__ int   sh_cnt[NWARP];
    __shared__ float sh_sc[NWARP];

    const int n    = blockIdx.x;
    const int tid  = threadIdx.x;
    const int lane = tid & 31;
    const int wid  = tid >> 5;
    const int L    = in_lens[n];             // input; overlaps kernel A via PDL
    const unsigned* __restrict__ gp = g_packed + n * TT;

    // Wait for kernel A completion (memory-visible).
    cudaGridDependencySynchronize();

    // Phase 1: load both chunks (coalesced)
    unsigned v[KITER];
#pragma unroll
    for (int k = 0; k < KITER; k++) {
        int t = tid + TPB * k;
        v[k] = (t < TT) ? gp[t] : 0u;
    }

    // Phase 2: default paths for ALL t (reference: argmax outside out_len)
#pragma unroll
    for (int k = 0; k < KITER; k++) {
        int t = tid + TPB * k;
        if (t < TT) out[NB + t * NB + n] = (float)(v[k] & 0xffffu);
    }
    __threadfence_block();
    __syncthreads();      // defaults ordered before compacted-prefix overwrite

    // Phase 3: keep-mask, scan, scatter, score (2 barriers per round)
    float score = 0.f;
    int base  = 0;
    int carry = 0;

#pragma unroll
    for (int k = 0; k < KITER; k++) {
        int   t = tid + TPB * k;
        int   a = (int)(v[k] & 0xffffu);
        float s = __half2float(__ushort_as_half((unsigned short)(v[k] >> 16)));

        sh_a[tid] = a;
        __syncthreads();                 // (1) sh_a visible

        int  aprev = (tid > 0) ? sh_a[tid - 1] : carry;
        carry = sh_a[TPB - 1];
        bool valid = (t < TT);
        bool inm   = valid && (t < L);
        bool keep  = inm && (a != 0) && (a != aprev || t == 0);
        if (inm) score += s;

        unsigned bal = __ballot_sync(FULLM, keep);
        if (lane == 0) sh_cnt[wid] = __popc(bal);
        __syncthreads();                 // (2) counts visible; all sh_a reads done

        // Warp-parallel scan over the 32 warp counts (every warp redundantly)
        int c0 = sh_cnt[lane];
        int c  = c0;
#pragma unroll
        for (int off = 1; off < 32; off <<= 1) {
            int y = __shfl_up_sync(FULLM, c, off);
            if (lane >= off) c += y;
        }
        int total  = __shfl_sync(FULLM, c, 31);
        int prefix = base + __shfl_sync(FULLM, c - c0, wid);  // exclusive for my warp

        if (keep) {
            int pos = prefix + __popc(bal & ((1u << lane) - 1u));
            out[NB + pos * NB + n] = (float)a;   // overwrite compacted prefix
        }
        base += total;
        // Safe to rewrite sh_a next round: all aprev reads preceded barrier (2).
    }

#pragma unroll
    for (int off = 16; off; off >>= 1)
        score += __shfl_xor_sync(FULLM, score, off);
    if (lane == 0) sh_sc[wid] = score;
    __syncthreads();

    if (wid == 0) {
        float x = sh_sc[lane];
#pragma unroll
        for (int off = 16; off; off >>= 1)
            x += __shfl_xor_sync(FULLM, x, off);
        if (lane == 0) {
            out[n] = x;                            // score
            out[NB + TT * NB + n] = (float)base;   // out_lens
        }
    }
}

extern "C" void kernel_launch(void* const* d_in, const int* in_sizes, int n_in,
                              void* d_out, int out_size)
{
    const float* logits  = (const float*)d_in[0];
    const int*   in_lens = (const int*)d_in[1];
    float*       out     = (float*)d_out;

    rowreduce_kernel<<<ROWS / 8, 256>>>(logits);

    // Programmatic dependent launch: compact dispatches early, overlaps its
    // prologue with rowreduce's tail, syncs on grid dependency internally.
    cudaLaunchConfig_t cfg = {};
    cfg.gridDim  = dim3(NB, 1, 1);
    cfg.blockDim = dim3(TPB, 1, 1);
    cfg.dynamicSmemBytes = 0;
    cfg.stream = 0;
    cudaLaunchAttribute attr[1];
    attr[0].id = cudaLaunchAttributeProgrammaticStreamSerialization;
    attr[0].val.programmaticStreamSerializationAllowed = 1;
    cfg.attrs = attr;
    cfg.numAttrs = 1;
    cudaLaunchKernelEx(&cfg, compact_kernel, in_lens, out);
}

// round 17
// speedup vs baseline: 1.0402x; 1.0402x over previous
#include <cuda_runtime.h>
#include <cuda_bf16.h>
#include <cuda_fp16.h>

#define TT 2000
#define NB 64
#define VV 1000
#define ROWS (TT * NB)
#define NEG_BIG (-1e30f)
#define TPB 1024
#define KITER 2           // ceil(TT / TPB)
#define NWARP (TPB / 32)  // 32
#define FULLM 0xffffffffu

// Scratch (no allocation allowed). n-major packed:
//   lo16 = argmax (V=1000 < 65536), hi16 = fp16 bits of maxlp.
__device__ unsigned g_packed[NB * TT];

// ---------------------------------------------------------------------------
// Kernel A: warp-per-row reduction over V=1000. Fence-free streaming hot loop.
// ---------------------------------------------------------------------------
__global__ __launch_bounds__(256) void rowreduce_kernel(
    const float* __restrict__ logits, float* __restrict__ out)
{
    const int row  = blockIdx.x * 8 + (threadIdx.x >> 5);  // row = t*NB + n
    const int lane = threadIdx.x & 31;

    const float4* __restrict__ p =
        reinterpret_cast<const float4*>(logits + (size_t)row * VV);

    // V=1000 floats = 250 float4; lane takes indices lane + 32*j, j<8.
    float4 v[8];
#pragma unroll
    for (int j = 0; j < 8; j++) {
        int idx = lane + 32 * j;
        if (idx < 250) v[j] = p[idx];
        else           v[j] = make_float4(NEG_BIG, NEG_BIG, NEG_BIG, NEG_BIG);
    }

    float m = NEG_BIG; int am = 0;
#pragma unroll
    for (int j = 0; j < 8; j++) {
        int base = (lane + 32 * j) * 4;
        float x;
        x = v[j].x; if (x > m) { m = x; am = base;     }
        x = v[j].y; if (x > m) { m = x; am = base + 1; }
        x = v[j].z; if (x > m) { m = x; am = base + 2; }
        x = v[j].w; if (x > m) { m = x; am = base + 3; }
    }
#pragma unroll
    for (int off = 16; off; off >>= 1) {
        float om = __shfl_xor_sync(FULLM, m,  off);
        int   oa = __shfl_xor_sync(FULLM, am, off);
        if (om > m || (om == m && oa < am)) { m = om; am = oa; }
    }

    float s = 0.f;
#pragma unroll
    for (int j = 0; j < 8; j++) {
        s += __expf(v[j].x - m) + __expf(v[j].y - m)
           + __expf(v[j].z - m) + __expf(v[j].w - m);
    }
#pragma unroll
    for (int off = 16; off; off >>= 1)
        s += __shfl_xor_sync(FULLM, s, off);

    if (lane == 0) {
        float maxlp = -__logf(s);            // max - lse
        int t = row >> 6;                    // NB == 64
        int n = row & (NB - 1);
        unsigned hb = (unsigned)__half_as_ushort(__float2half_rn(maxlp));
        g_packed[n * TT + t] = (hb << 16) | (unsigned)am;
        out[NB + row] = (float)am;           // default paths (t-major)
    }
}

// ---------------------------------------------------------------------------
// Kernel B: block-per-n compaction + score. PDL: prologue runs overlapped with
// kernel A's tail; grid-dependency sync before any g_packed read.
// ---------------------------------------------------------------------------
__global__ __launch_bounds__(TPB) void compact_kernel(
    const int* __restrict__ in_lens, float* __restrict__ out)
{
    __shared__ int   sh_a[TPB];
    __shared__ int   sh_cnt[NWARP];
    __shared__ float sh_sc[NWARP];

    const int n    = blockIdx.x;
    const int tid  = threadIdx.x;
    const int lane = tid & 31;
    const int wid  = tid >> 5;
    const int L    = in_lens[n];             // input, not produced by kernel A
    const unsigned* __restrict__ gp = g_packed + n * TT;

    // Wait for kernel A's completion (memory-visible) before reading scratch.
    cudaGridDependencySynchronize();

    // Prefetch both chunks (coalesced, overlapped)
    unsigned v[KITER];
#pragma unroll
    for (int k = 0; k < KITER; k++) {
        int t = tid + TPB * k;
        v[k] = (t < TT) ? gp[t] : 0u;
    }

    float score = 0.f;
    int base  = 0;   // running kept count == final out_len
    int carry = 0;   // argmax at (chunk_base - 1)

#pragma unroll
    for (int k = 0; k < KITER; k++) {
        int   t = tid + TPB * k;
        int   a = (int)(v[k] & 0xffffu);
        float s = __half2float(__ushort_as_half((unsigned short)(v[k] >> 16)));

        __syncthreads();                 // protect sh_a/sh_cnt reuse
        sh_a[tid] = a;
        __syncthreads();

        int  aprev = (tid > 0) ? sh_a[tid - 1] : carry;
        bool valid = (t < TT);
        bool inm   = valid && (t < L);
        bool keep  = inm && (a != 0) && (a != aprev || t == 0);
        if (inm) score += s;

        unsigned bal = __ballot_sync(FULLM, keep);
        if (lane == 0) sh_cnt[wid] = __popc(bal);
        __syncthreads();

        // Warp-parallel scan over the 32 warp counts (every warp redundantly)
        int c0 = sh_cnt[lane];
        int c  = c0;
#pragma unroll
        for (int off = 1; off < 32; off <<= 1) {
            int y = __shfl_up_sync(FULLM, c, off);
            if (lane >= off) c += y;
        }
        int total  = __shfl_sync(FULLM, c, 31);
        int prefix = base + __shfl_sync(FULLM, c - c0, wid);  // exclusive for my warp

        if (keep) {
            int pos = prefix + __popc(bal & ((1u << lane) - 1u));
            out[NB + pos * NB + n] = (float)a;   // overwrite compacted prefix
        }
        base += total;
        carry = sh_a[TPB - 1];
    }

#pragma unroll
    for (int off = 16; off; off >>= 1)
        score += __shfl_xor_sync(FULLM, score, off);
    if (lane == 0) sh_sc[wid] = score;
    __syncthreads();

    if (wid == 0) {
        float x = sh_sc[lane];
#pragma unroll
        for (int off = 16; off; off >>= 1)
            x += __shfl_xor_sync(FULLM, x, off);
        if (lane == 0) {
            out[n] = x;                            // score
            out[NB + TT * NB + n] = (float)base;   // out_lens
        }
    }
}

extern "C" void kernel_launch(void* const* d_in, const int* in_sizes, int n_in,
                              void* d_out, int out_size)
{
    const float* logits  = (const float*)d_in[0];
    const int*   in_lens = (const int*)d_in[1];
    float*       out     = (float*)d_out;

    rowreduce_kernel<<<ROWS / 8, 256>>>(logits, out);

    // Programmatic dependent launch: compact dispatches early, overlaps its
    // ramp with rowreduce's tail wave, syncs on grid dependency internally.
    cudaLaunchConfig_t cfg = {};
    cfg.gridDim  = dim3(NB, 1, 1);
    cfg.blockDim = dim3(TPB, 1, 1);
    cfg.dynamicSmemBytes = 0;
    cfg.stream = 0;
    cudaLaunchAttribute attr[1];
    attr[0].id = cudaLaunchAttributeProgrammaticStreamSerialization;
    attr[0].val.programmaticStreamSerializationAllowed = 1;
    cfg.attrs = attr;
    cfg.numAttrs = 1;
    cudaLaunchKernelEx(&cfg, compact_kernel, in_lens, out);
}